// round 3
// baseline (speedup 1.0000x reference)
#include <cuda_runtime.h>
#include <cuda_bf16.h>
#include <cstdint>

// DiceLoss: pred (8,19,512,512) fp32 logits, target (8,512,512) int32 -> scalar fp32.
//
// One pass over pred, float2-vectorized. Per pixel-pair: packed f32x2 polynomial
// exp (FMA pipe, no MUFU), packed per-class register accumulators (halves =
// the two pixels), per-warp shared atomics for intersection/count keyed by the
// target label (e[t] recomputed from an L1-hit reload). Deterministic 2-stage
// reduction via __device__ scratch (no allocations).

static constexpr int B   = 8;
static constexpr int C   = 19;
static constexpr int HW  = 512 * 512;           // 262144
static constexpr int BLOCK = 256;
static constexpr int PPT   = 8;                 // pixels per thread (4 pairs)
static constexpr int PAIRS = PPT / 2;
static constexpr int PIX_PER_BLOCK = BLOCK * PPT;              // 2048
static constexpr int BLOCKS_PER_BATCH = HW / PIX_PER_BLOCK;    // 128
static constexpr int NBLK = B * BLOCKS_PER_BATCH;              // 1024
static constexpr float SMOOTH = 1e-5f;
static constexpr int IGNORE_INDEX = 255;

// Scratch partials (fully overwritten every launch -> no init needed).
__device__ float g_pm   [NBLK * C];
__device__ float g_inter[NBLK * C];
__device__ float g_cnt  [NBLK * C];

// ---------- packed f32x2 helpers (Blackwell sm_103a) ----------
__device__ __forceinline__ unsigned long long pk2(float a, float b) {
    unsigned long long r;
    asm("mov.b64 %0, {%1, %2};" : "=l"(r) : "f"(a), "f"(b));
    return r;
}
__device__ __forceinline__ unsigned long long mul2(unsigned long long a, unsigned long long b) {
    unsigned long long r;
    asm("mul.rn.f32x2 %0, %1, %2;" : "=l"(r) : "l"(a), "l"(b));
    return r;
}
__device__ __forceinline__ unsigned long long add2(unsigned long long a, unsigned long long b) {
    unsigned long long r;
    asm("add.rn.f32x2 %0, %1, %2;" : "=l"(r) : "l"(a), "l"(b));
    return r;
}
__device__ __forceinline__ unsigned long long fma2(unsigned long long a, unsigned long long b,
                                                   unsigned long long c) {
    unsigned long long r;
    asm("fma.rn.f32x2 %0, %1, %2, %3;" : "=l"(r) : "l"(a), "l"(b), "l"(c));
    return r;
}
__device__ __forceinline__ void upk2f(unsigned long long v, float& a, float& b) {
    asm("mov.b64 {%0, %1}, %2;" : "=f"(a), "=f"(b) : "l"(v));
}
__device__ __forceinline__ void upk2u(unsigned long long v, unsigned& a, unsigned& b) {
    asm("mov.b64 {%0, %1}, %2;" : "=r"(a), "=r"(b) : "l"(v));
}
__device__ __forceinline__ unsigned long long pk2u(unsigned a, unsigned b) {
    unsigned long long r;
    asm("mov.b64 %0, {%1, %2};" : "=l"(r) : "r"(a), "r"(b));
    return r;
}

// e^x for two floats at once: 2^(x*log2e) via magic-number round + deg-4 poly.
// Magic = 1.5*2^23: float_bits(t+MAGIC) = base + round(t); (base+n)<<23 ==
// n<<23 (mod 2^32), so the exponent splice is one shift+add per half (alu pipe).
// Valid for |x| < ~87 (inputs are N(0,1) logits). Rel err ~3e-5.
__device__ __forceinline__ unsigned long long exp_pair(float x0, float x1) {
    const unsigned long long L2E2 = pk2(1.4426950408889634f, 1.4426950408889634f);
    const unsigned long long MG2  = pk2(12582912.0f, 12582912.0f);
    const unsigned long long NMG2 = pk2(-12582912.0f, -12582912.0f);
    const unsigned long long M12  = pk2(-1.0f, -1.0f);
    const unsigned long long C4   = pk2(9.6181291e-3f, 9.6181291e-3f);
    const unsigned long long C3   = pk2(5.5504109e-2f, 5.5504109e-2f);
    const unsigned long long C2   = pk2(2.4022651e-1f, 2.4022651e-1f);
    const unsigned long long C1   = pk2(6.9314718e-1f, 6.9314718e-1f);
    const unsigned long long ONE  = pk2(1.0f, 1.0f);

    unsigned long long X = pk2(x0, x1);
    unsigned long long T = mul2(X, L2E2);
    unsigned long long Z = add2(T, MG2);        // mantissa bits hold round(t)
    unsigned long long R = add2(Z, NMG2);       // r = round(t) as float
    unsigned long long F = fma2(R, M12, T);     // f = t - r, in [-0.5, 0.5]
    unsigned long long P = fma2(C4, F, C3);
    P = fma2(P, F, C2);
    P = fma2(P, F, C1);
    P = fma2(P, F, ONE);
    unsigned z0, z1, p0, p1;
    upk2u(Z, z0, z1);
    upk2u(P, p0, p1);
    return pk2u(p0 + (z0 << 23), p1 + (z1 << 23));
}

__device__ __forceinline__ float exp_scalar(float x) {
    const float L2E   = 1.4426950408889634f;
    const float MAGIC = 12582912.0f;
    float t = x * L2E;
    float z = t + MAGIC;
    unsigned n = __float_as_uint(z);
    float f = t - (z - MAGIC);
    float p = 9.6181291e-3f;
    p = fmaf(p, f, 5.5504109e-2f);
    p = fmaf(p, f, 2.4022651e-1f);
    p = fmaf(p, f, 6.9314718e-1f);
    p = fmaf(p, f, 1.0f);
    return __uint_as_float(__float_as_uint(p) + (n << 23));
}

__global__ __launch_bounds__(BLOCK, 2)
void dice_main_kernel(const float* __restrict__ pred,
                      const int*   __restrict__ target) {
    const int blk   = blockIdx.x;
    const int b     = blk / BLOCKS_PER_BATCH;
    const int chunk = blk % BLOCKS_PER_BATCH;
    const int tid   = threadIdx.x;
    const int warp  = tid >> 5;
    const int lane  = tid & 31;

    __shared__ float sh_inter[8][C];   // per-warp privatized
    __shared__ float sh_cnt  [8][C];
    __shared__ float sh_pm   [8][C];

    for (int i = tid; i < 8 * C; i += BLOCK) {
        (&sh_inter[0][0])[i] = 0.0f;
        (&sh_cnt  [0][0])[i] = 0.0f;
    }
    __syncthreads();

    const float* __restrict__ pb = pred + (size_t)b * C * HW;
    const int*   __restrict__ tb = target + (size_t)b * HW;
    const int hw0 = chunk * PIX_PER_BLOCK;

    // Packed per-class accumulators; halves = the two pixels of each pair.
    unsigned long long acc2[C];
    #pragma unroll
    for (int c = 0; c < C; c++) acc2[c] = pk2(0.0f, 0.0f);

    #pragma unroll
    for (int j = 0; j < PAIRS; j++) {
        const int base = hw0 + j * (BLOCK * 2) + tid * 2;   // even; coalesced
        const int2 t2 = *(const int2*)(tb + base);

        unsigned long long e2[C];
        unsigned long long S2 = pk2(0.0f, 0.0f);
        #pragma unroll
        for (int c = 0; c < C; c++) {
            const float2 x = *(const float2*)(pb + (size_t)c * HW + base);
            e2[c] = exp_pair(x.x, x.y);
            S2 = add2(S2, e2[c]);
        }
        float s0, s1;
        upk2f(S2, s0, s1);

        const bool m0 = (t2.x != IGNORE_INDEX);
        const bool m1 = (t2.y != IGNORE_INDEX);
        const float inv0 = m0 ? __fdividef(1.0f, s0) : 0.0f;  // MUFU.RCP
        const float inv1 = m1 ? __fdividef(1.0f, s1) : 0.0f;
        const unsigned long long inv2 = pk2(inv0, inv1);

        #pragma unroll
        for (int c = 0; c < C; c++)
            acc2[c] = fma2(e2[c], inv2, acc2[c]);

        // e[target]: reload the logit (L1 hit, line fetched this iteration).
        if (m0) {
            const float et = exp_scalar(pb[(size_t)t2.x * HW + base]);
            atomicAdd(&sh_inter[warp][t2.x], et * inv0);
            atomicAdd(&sh_cnt  [warp][t2.x], 1.0f);
        }
        if (m1) {
            const float et = exp_scalar(pb[(size_t)t2.y * HW + base + 1]);
            atomicAdd(&sh_inter[warp][t2.y], et * inv1);
            atomicAdd(&sh_cnt  [warp][t2.y], 1.0f);
        }
    }

    // Warp-reduce register accumulators, stage per warp (deterministic order).
    #pragma unroll
    for (int c = 0; c < C; c++) {
        float lo, hi;
        upk2f(acc2[c], lo, hi);
        float v = lo + hi;
        v += __shfl_xor_sync(0xffffffffu, v, 16);
        v += __shfl_xor_sync(0xffffffffu, v, 8);
        v += __shfl_xor_sync(0xffffffffu, v, 4);
        v += __shfl_xor_sync(0xffffffffu, v, 2);
        v += __shfl_xor_sync(0xffffffffu, v, 1);
        if (lane == 0) sh_pm[warp][c] = v;
    }
    __syncthreads();

    // Fixed-order fold across the 8 warps -> per-block partials.
    if (tid < C) {
        float pm = 0.0f, it = 0.0f, ct = 0.0f;
        #pragma unroll
        for (int w = 0; w < 8; w++) {
            pm += sh_pm[w][tid];
            it += sh_inter[w][tid];
            ct += sh_cnt[w][tid];
        }
        g_pm   [blk * C + tid] = pm;
        g_inter[blk * C + tid] = it;
        g_cnt  [blk * C + tid] = ct;
    }
}

__global__ __launch_bounds__(256)
void dice_reduce_kernel(float* __restrict__ out) {
    __shared__ float sh[256];
    const int tid = threadIdx.x;
    float v = 0.0f;
    if (tid < B * C) {
        const int b = tid / C;
        const int c = tid % C;
        float pm = 0.0f, it = 0.0f, ct = 0.0f;
        const int base = b * BLOCKS_PER_BATCH;
        for (int k = 0; k < BLOCKS_PER_BATCH; k++) {
            const int idx = (base + k) * C + c;
            pm += g_pm[idx];
            it += g_inter[idx];
            ct += g_cnt[idx];
        }
        const float uni = pm + ct;
        const float dc  = (2.0f * it + SMOOTH) / (uni + SMOOTH);
        v = 1.0f - dc;
    }
    sh[tid] = v;
    __syncthreads();
    #pragma unroll
    for (int s = 128; s > 0; s >>= 1) {
        if (tid < s) sh[tid] += sh[tid + s];
        __syncthreads();
    }
    if (tid == 0) out[0] = sh[0] * (1.0f / (float)(B * C));
}

extern "C" void kernel_launch(void* const* d_in, const int* in_sizes, int n_in,
                              void* d_out, int out_size) {
    const float* pred   = (const float*)d_in[0];
    const int*   target = (const int*)d_in[1];
    float*       out    = (float*)d_out;
    (void)in_sizes; (void)n_in; (void)out_size;

    dice_main_kernel<<<NBLK, BLOCK>>>(pred, target);
    dice_reduce_kernel<<<1, 256>>>(out);
}

// round 4
// speedup vs baseline: 1.2985x; 1.2985x over previous
#include <cuda_runtime.h>
#include <cuda_bf16.h>
#include <cstdint>

// DiceLoss: pred (8,19,512,512) fp32 logits, target (8,512,512) int32 -> scalar fp32.
//
// Single fused kernel: one pass over pred (float2-vectorized, packed f32x2
// deg-3 polynomial exp on the FMA pipe), per-warp shared atomics for
// intersection/count, per-block partials to __device__ scratch, and a
// last-block-done finalize (partials are L2-hot). Deterministic; counter
// self-resets so the kernel is graph-replay safe.

static constexpr int B   = 8;
static constexpr int C   = 19;
static constexpr int HW  = 512 * 512;           // 262144
static constexpr int BLOCK = 256;
static constexpr int PPT   = 8;                 // pixels per thread (4 pairs)
static constexpr int PAIRS = PPT / 2;
static constexpr int PIX_PER_BLOCK = BLOCK * PPT;              // 2048
static constexpr int BLOCKS_PER_BATCH = HW / PIX_PER_BLOCK;    // 128
static constexpr int NBLK = B * BLOCKS_PER_BATCH;              // 1024
static constexpr float SMOOTH = 1e-5f;
static constexpr int IGNORE_INDEX = 255;

// Scratch partials (fully overwritten every launch -> no init needed).
__device__ float g_pm   [NBLK * C];
__device__ float g_inter[NBLK * C];
__device__ float g_cnt  [NBLK * C];
__device__ int   g_done;                        // zero-init; reset by final block

// ---------- packed f32x2 helpers (Blackwell sm_103a) ----------
__device__ __forceinline__ unsigned long long pk2(float a, float b) {
    unsigned long long r;
    asm("mov.b64 %0, {%1, %2};" : "=l"(r) : "f"(a), "f"(b));
    return r;
}
__device__ __forceinline__ unsigned long long add2(unsigned long long a, unsigned long long b) {
    unsigned long long r;
    asm("add.rn.f32x2 %0, %1, %2;" : "=l"(r) : "l"(a), "l"(b));
    return r;
}
__device__ __forceinline__ unsigned long long fma2(unsigned long long a, unsigned long long b,
                                                   unsigned long long c) {
    unsigned long long r;
    asm("fma.rn.f32x2 %0, %1, %2, %3;" : "=l"(r) : "l"(a), "l"(b), "l"(c));
    return r;
}
__device__ __forceinline__ void upk2f(unsigned long long v, float& a, float& b) {
    asm("mov.b64 {%0, %1}, %2;" : "=f"(a), "=f"(b) : "l"(v));
}
__device__ __forceinline__ void upk2u(unsigned long long v, unsigned& a, unsigned& b) {
    asm("mov.b64 {%0, %1}, %2;" : "=r"(a), "=r"(b) : "l"(v));
}
__device__ __forceinline__ unsigned long long pk2u(unsigned a, unsigned b) {
    unsigned long long r;
    asm("mov.b64 %0, {%1, %2};" : "=l"(r) : "r"(a), "r"(b));
    return r;
}

// exp coefficients: deg-3 poly for 2^f on f in [-0.5,0.5], Chebyshev-corrected
// (projects the dropped f^4/f^5 Taylor terms down; rel err ~1e-4).
// We evaluate in G = round(t) - t = -f, so odd coefficients carry flipped sign:
// p = ((NC3*G + PC2)*G + NC1)*G + PC0.
#define EXP_L2E   1.4426950408889634f
#define EXP_NL2E  (-1.4426950408889634f)
#define EXP_MAGIC 12582912.0f                   // 1.5 * 2^23
#define EXP_PC0   0.99992486f
#define EXP_NC1   (-0.69312114f)
#define EXP_PC2   0.24263101f
#define EXP_NC3   (-0.05592081f)

// e^x for two floats at once. Z = fma(x, log2e, MAGIC): mantissa low bits hold
// round(t), and (bits(Z) << 23) == round(t) << 23 (mod 2^32) -> exponent splice
// is one shift+add per half on the alu pipe. 6 fma-pipe ops total.
__device__ __forceinline__ unsigned long long exp_pair(float x0, float x1) {
    const unsigned long long L2E2  = pk2(EXP_L2E, EXP_L2E);
    const unsigned long long NL2E2 = pk2(EXP_NL2E, EXP_NL2E);
    const unsigned long long MG2   = pk2(EXP_MAGIC, EXP_MAGIC);
    const unsigned long long NMG2  = pk2(-EXP_MAGIC, -EXP_MAGIC);
    const unsigned long long K3    = pk2(EXP_NC3, EXP_NC3);
    const unsigned long long K2    = pk2(EXP_PC2, EXP_PC2);
    const unsigned long long K1    = pk2(EXP_NC1, EXP_NC1);
    const unsigned long long K0    = pk2(EXP_PC0, EXP_PC0);

    unsigned long long X = pk2(x0, x1);
    unsigned long long Z = fma2(X, L2E2, MG2);   // bits: base + round(t)
    unsigned long long R = add2(Z, NMG2);        // round(t) as float
    unsigned long long G = fma2(X, NL2E2, R);    // r - t = -f, in [-0.5, 0.5]
    unsigned long long P = fma2(K3, G, K2);
    P = fma2(P, G, K1);
    P = fma2(P, G, K0);
    unsigned z0, z1, p0, p1;
    upk2u(Z, z0, z1);
    upk2u(P, p0, p1);
    return pk2u(p0 + (z0 << 23), p1 + (z1 << 23));
}

__device__ __forceinline__ float exp_scalar(float x) {
    float z = fmaf(x, EXP_L2E, EXP_MAGIC);
    unsigned n = __float_as_uint(z);
    float g = fmaf(x, EXP_NL2E, z - EXP_MAGIC);  // -f
    float p = fmaf(EXP_NC3, g, EXP_PC2);
    p = fmaf(p, g, EXP_NC1);
    p = fmaf(p, g, EXP_PC0);
    return __uint_as_float(__float_as_uint(p) + (n << 23));
}

__global__ __launch_bounds__(BLOCK, 2)
void dice_main_kernel(const float* __restrict__ pred,
                      const int*   __restrict__ target,
                      float*       __restrict__ out) {
    const int blk   = blockIdx.x;
    const int b     = blk / BLOCKS_PER_BATCH;
    const int chunk = blk % BLOCKS_PER_BATCH;
    const int tid   = threadIdx.x;
    const int warp  = tid >> 5;
    const int lane  = tid & 31;

    __shared__ float sh_inter[8][C];   // per-warp privatized
    __shared__ float sh_cnt  [8][C];
    __shared__ float sh_pm   [8][C];
    __shared__ int   sh_last;

    for (int i = tid; i < 8 * C; i += BLOCK) {
        (&sh_inter[0][0])[i] = 0.0f;
        (&sh_cnt  [0][0])[i] = 0.0f;
    }
    __syncthreads();

    const float* __restrict__ pb = pred + (size_t)b * C * HW;
    const int*   __restrict__ tb = target + (size_t)b * HW;
    const int hw0 = chunk * PIX_PER_BLOCK;

    // Packed per-class accumulators; halves = the two pixels of each pair.
    unsigned long long acc2[C];
    #pragma unroll
    for (int c = 0; c < C; c++) acc2[c] = pk2(0.0f, 0.0f);

    #pragma unroll
    for (int j = 0; j < PAIRS; j++) {
        const int base = hw0 + j * (BLOCK * 2) + tid * 2;   // even; coalesced
        const int2 t2 = *(const int2*)(tb + base);

        unsigned long long e2[C];
        unsigned long long S2 = pk2(0.0f, 0.0f);
        #pragma unroll
        for (int c = 0; c < C; c++) {
            const float2 x = *(const float2*)(pb + (size_t)c * HW + base);
            e2[c] = exp_pair(x.x, x.y);
            S2 = add2(S2, e2[c]);
        }
        float s0, s1;
        upk2f(S2, s0, s1);

        const bool m0 = (t2.x != IGNORE_INDEX);
        const bool m1 = (t2.y != IGNORE_INDEX);
        const float inv0 = m0 ? __fdividef(1.0f, s0) : 0.0f;  // MUFU.RCP
        const float inv1 = m1 ? __fdividef(1.0f, s1) : 0.0f;
        const unsigned long long inv2 = pk2(inv0, inv1);

        #pragma unroll
        for (int c = 0; c < C; c++)
            acc2[c] = fma2(e2[c], inv2, acc2[c]);

        // e[target]: reload the logit (L1 hit, line fetched this iteration).
        if (m0) {
            const float et = exp_scalar(pb[(size_t)t2.x * HW + base]);
            atomicAdd(&sh_inter[warp][t2.x], et * inv0);
            atomicAdd(&sh_cnt  [warp][t2.x], 1.0f);
        }
        if (m1) {
            const float et = exp_scalar(pb[(size_t)t2.y * HW + base + 1]);
            atomicAdd(&sh_inter[warp][t2.y], et * inv1);
            atomicAdd(&sh_cnt  [warp][t2.y], 1.0f);
        }
    }

    // Warp-reduce register accumulators, stage per warp (deterministic order).
    #pragma unroll
    for (int c = 0; c < C; c++) {
        float lo, hi;
        upk2f(acc2[c], lo, hi);
        float v = lo + hi;
        v += __shfl_xor_sync(0xffffffffu, v, 16);
        v += __shfl_xor_sync(0xffffffffu, v, 8);
        v += __shfl_xor_sync(0xffffffffu, v, 4);
        v += __shfl_xor_sync(0xffffffffu, v, 2);
        v += __shfl_xor_sync(0xffffffffu, v, 1);
        if (lane == 0) sh_pm[warp][c] = v;
    }
    __syncthreads();

    // Fixed-order fold across the 8 warps -> per-block partials.
    if (tid < C) {
        float pm = 0.0f, it = 0.0f, ct = 0.0f;
        #pragma unroll
        for (int w = 0; w < 8; w++) {
            pm += sh_pm[w][tid];
            it += sh_inter[w][tid];
            ct += sh_cnt[w][tid];
        }
        g_pm   [blk * C + tid] = pm;
        g_inter[blk * C + tid] = it;
        g_cnt  [blk * C + tid] = ct;
        __threadfence();                       // publish before counting
    }
    __syncthreads();

    if (tid == 0) {
        const int old = atomicAdd(&g_done, 1);
        sh_last = (old == NBLK - 1);
    }
    __syncthreads();
    if (!sh_last) return;

    // ---- last-block finalize (partials are L2-hot) ----
    __threadfence();                           // acquire partials
    __shared__ float sh_red[BLOCK];
    float v = 0.0f;
    if (tid < B * C) {
        const int bb = tid / C;
        const int cc = tid % C;
        float pm = 0.0f, it = 0.0f, ct = 0.0f;
        const int base = bb * BLOCKS_PER_BATCH;
        #pragma unroll 8
        for (int k = 0; k < BLOCKS_PER_BATCH; k++) {
            const int idx = (base + k) * C + cc;
            pm += g_pm[idx];
            it += g_inter[idx];
            ct += g_cnt[idx];
        }
        const float uni = pm + ct;
        const float dc  = (2.0f * it + SMOOTH) / (uni + SMOOTH);
        v = 1.0f - dc;
    }
    sh_red[tid] = v;
    __syncthreads();
    #pragma unroll
    for (int s = 128; s > 0; s >>= 1) {
        if (tid < s) sh_red[tid] += sh_red[tid + s];
        __syncthreads();
    }
    if (tid == 0) {
        out[0] = sh_red[0] * (1.0f / (float)(B * C));
        g_done = 0;                            // reset for next (graph) launch
    }
}

extern "C" void kernel_launch(void* const* d_in, const int* in_sizes, int n_in,
                              void* d_out, int out_size) {
    const float* pred   = (const float*)d_in[0];
    const int*   target = (const int*)d_in[1];
    float*       out    = (float*)d_out;
    (void)in_sizes; (void)n_in; (void)out_size;

    dice_main_kernel<<<NBLK, BLOCK>>>(pred, target, out);
}

// round 9
// speedup vs baseline: 1.3973x; 1.0760x over previous
#include <cuda_runtime.h>
#include <cuda_bf16.h>
#include <cstdint>

// DiceLoss: pred (8,19,512,512) fp32 logits, target (8,512,512) int32 -> scalar fp32.
//
// Single fused kernel, latency-optimized:
//  * 19 classes split across 4 threads (g = tid&3 owns 5 slots, last padded)
//    -> ~20 regs packed state, 4 blocks/SM (occ 50%). Softmax sum completed
//    with 2 packed butterfly shuffles.
//  * 512 blocks, each handling 2 chunks of one batch -> single resident wave
//    at 4 blocks/SM (no wave tail).
//  * Packed f32x2 deg-3 polynomial exp on the FMA pipe (no MUFU).
//  * Per-warp shared atomics for intersection/count.
//  * Last-block-done finalize; counter self-resets (graph-replay safe).

static constexpr int B   = 8;
static constexpr int C   = 19;
static constexpr int CG  = 4;                   // class groups (threads per pixel-pair)
static constexpr int NCG = 5;                   // class slots per group (last padded)
static constexpr int HW  = 512 * 512;           // 262144
static constexpr int BLOCK = 256;
static constexpr int PAIRS_PER_ITER = BLOCK / CG;              // 64 pixel-pairs
static constexpr int ITERS = 16;                               // per chunk
static constexpr int PIX_PER_CHUNK = PAIRS_PER_ITER * 2 * ITERS;   // 2048
static constexpr int CHUNKS_PER_BATCH = HW / PIX_PER_CHUNK;    // 128
static constexpr int CHUNKS_PER_BLK = 2;
static constexpr int GRPS_PER_BATCH = CHUNKS_PER_BATCH / CHUNKS_PER_BLK;  // 64
static constexpr int NBLK = B * GRPS_PER_BATCH;                // 512 (single wave)
static constexpr float SMOOTH = 1e-5f;
static constexpr int IGNORE_INDEX = 255;

// Scratch partials (fully overwritten every launch -> no init needed).
__device__ float g_pm   [NBLK * C];
__device__ float g_inter[NBLK * C];
__device__ float g_cnt  [NBLK * C];
__device__ int   g_done;                        // zero-init; reset by final block

// ---------- packed f32x2 helpers (Blackwell sm_103a) ----------
__device__ __forceinline__ unsigned long long pk2(float a, float b) {
    unsigned long long r;
    asm("mov.b64 %0, {%1, %2};" : "=l"(r) : "f"(a), "f"(b));
    return r;
}
__device__ __forceinline__ unsigned long long add2(unsigned long long a, unsigned long long b) {
    unsigned long long r;
    asm("add.rn.f32x2 %0, %1, %2;" : "=l"(r) : "l"(a), "l"(b));
    return r;
}
__device__ __forceinline__ unsigned long long fma2(unsigned long long a, unsigned long long b,
                                                   unsigned long long c) {
    unsigned long long r;
    asm("fma.rn.f32x2 %0, %1, %2, %3;" : "=l"(r) : "l"(a), "l"(b), "l"(c));
    return r;
}
__device__ __forceinline__ void upk2f(unsigned long long v, float& a, float& b) {
    asm("mov.b64 {%0, %1}, %2;" : "=f"(a), "=f"(b) : "l"(v));
}
__device__ __forceinline__ void upk2u(unsigned long long v, unsigned& a, unsigned& b) {
    asm("mov.b64 {%0, %1}, %2;" : "=r"(a), "=r"(b) : "l"(v));
}
__device__ __forceinline__ unsigned long long pk2u(unsigned a, unsigned b) {
    unsigned long long r;
    asm("mov.b64 %0, {%1, %2};" : "=l"(r) : "r"(a), "r"(b));
    return r;
}
__device__ __forceinline__ unsigned long long shfl2_xor(unsigned long long v, int m) {
    unsigned lo, hi;
    upk2u(v, lo, hi);
    lo = __shfl_xor_sync(0xffffffffu, lo, m);
    hi = __shfl_xor_sync(0xffffffffu, hi, m);
    return pk2u(lo, hi);
}

// exp: deg-3 poly for 2^f on f in [-0.5,0.5], Chebyshev-corrected (rel err
// ~1e-4; cancels to ~1e-5 in the final dice ratio). Evaluated in
// G = round(t) - t = -f, so odd coefficients carry flipped sign.
#define EXP_L2E   1.4426950408889634f
#define EXP_NL2E  (-1.4426950408889634f)
#define EXP_MAGIC 12582912.0f                   // 1.5 * 2^23
#define EXP_PC0   0.99992486f
#define EXP_NC1   (-0.69312114f)
#define EXP_PC2   0.24263101f
#define EXP_NC3   (-0.05592081f)

// e^x for two floats at once. Z = fma(x, log2e, MAGIC): mantissa low bits hold
// round(t); (bits(Z) << 23) == round(t) << 23 (mod 2^32) -> exponent splice is
// one shift+add per half on the alu pipe. 6 fma-pipe ops total.
__device__ __forceinline__ unsigned long long exp_pair(float x0, float x1) {
    const unsigned long long L2E2  = pk2(EXP_L2E, EXP_L2E);
    const unsigned long long NL2E2 = pk2(EXP_NL2E, EXP_NL2E);
    const unsigned long long MG2   = pk2(EXP_MAGIC, EXP_MAGIC);
    const unsigned long long NMG2  = pk2(-EXP_MAGIC, -EXP_MAGIC);
    const unsigned long long K3    = pk2(EXP_NC3, EXP_NC3);
    const unsigned long long K2    = pk2(EXP_PC2, EXP_PC2);
    const unsigned long long K1    = pk2(EXP_NC1, EXP_NC1);
    const unsigned long long K0    = pk2(EXP_PC0, EXP_PC0);

    unsigned long long X = pk2(x0, x1);
    unsigned long long Z = fma2(X, L2E2, MG2);   // bits: base + round(t)
    unsigned long long R = add2(Z, NMG2);        // round(t) as float
    unsigned long long G = fma2(X, NL2E2, R);    // -f, in [-0.5, 0.5]
    unsigned long long P = fma2(K3, G, K2);
    P = fma2(P, G, K1);
    P = fma2(P, G, K0);
    unsigned z0, z1, p0, p1;
    upk2u(Z, z0, z1);
    upk2u(P, p0, p1);
    return pk2u(p0 + (z0 << 23), p1 + (z1 << 23));
}

__device__ __forceinline__ float exp_scalar(float x) {
    float z = fmaf(x, EXP_L2E, EXP_MAGIC);
    unsigned n = __float_as_uint(z);
    float g = fmaf(x, EXP_NL2E, z - EXP_MAGIC);  // -f
    float p = fmaf(EXP_NC3, g, EXP_PC2);
    p = fmaf(p, g, EXP_NC1);
    p = fmaf(p, g, EXP_PC0);
    return __uint_as_float(__float_as_uint(p) + (n << 23));
}

__global__ __launch_bounds__(BLOCK, 4)
void dice_main_kernel(const float* __restrict__ pred,
                      const int*   __restrict__ target,
                      float*       __restrict__ out) {
    const int blk   = blockIdx.x;
    const int b     = blk / GRPS_PER_BATCH;
    const int grp   = blk % GRPS_PER_BATCH;      // chunk group within batch
    const int tid   = threadIdx.x;
    const int warp  = tid >> 5;
    const int lane  = tid & 31;
    const int g     = tid & (CG - 1);            // class group 0..3
    const int pix   = tid >> 2;                  // pixel-pair slot 0..63

    __shared__ float sh_inter[8][C];   // per-warp privatized
    __shared__ float sh_cnt  [8][C];
    __shared__ float sh_pm   [8][C];
    __shared__ int   sh_last;

    for (int i = tid; i < 8 * C; i += BLOCK) {
        (&sh_inter[0][0])[i] = 0.0f;
        (&sh_cnt  [0][0])[i] = 0.0f;
    }
    __syncthreads();

    const float* __restrict__ pbg = pred + (size_t)b * C * HW + (size_t)(g * NCG) * HW;
    const int*   __restrict__ tb  = target + (size_t)b * HW;
    const bool has_pad = (g == CG - 1);          // group 3: slot 4 is padding

    // Packed per-class-slot accumulators; halves = the two pixels of a pair.
    unsigned long long acc2[NCG];
    #pragma unroll
    for (int k = 0; k < NCG; k++) acc2[k] = pk2(0.0f, 0.0f);

    for (int cc = 0; cc < CHUNKS_PER_BLK; cc++) {
        const int chunk = grp + cc * GRPS_PER_BATCH;   // grp and grp+64
        const int hw0 = chunk * PIX_PER_CHUNK;

        #pragma unroll 4
        for (int j = 0; j < ITERS; j++) {
            const int base = hw0 + j * (PAIRS_PER_ITER * 2) + pix * 2;
            const int2 t2 = *(const int2*)(tb + base);

            unsigned long long e2[NCG];
            #pragma unroll
            for (int k = 0; k < NCG; k++) {
                float2 x;
                if (k == NCG - 1 && has_pad) {
                    x.x = -88.0f; x.y = -88.0f;  // pad slot -> exp ~ 0
                } else {
                    x = *(const float2*)(pbg + (size_t)k * HW + base);
                }
                e2[k] = exp_pair(x.x, x.y);
            }
            // Tree-sum this thread's 5 slots (depth 3), then butterfly across
            // the 4 class groups (lanes g0..g3 of the same pixel pair).
            unsigned long long S2 = add2(add2(e2[0], e2[1]), add2(e2[2], e2[3]));
            S2 = add2(S2, e2[4]);
            S2 = add2(S2, shfl2_xor(S2, 1));
            S2 = add2(S2, shfl2_xor(S2, 2));

            float s0, s1;
            upk2f(S2, s0, s1);
            const bool m0 = (t2.x != IGNORE_INDEX);
            const bool m1 = (t2.y != IGNORE_INDEX);
            const float inv0 = m0 ? __fdividef(1.0f, s0) : 0.0f;  // MUFU.RCP
            const float inv1 = m1 ? __fdividef(1.0f, s1) : 0.0f;
            const unsigned long long inv2 = pk2(inv0, inv1);

            #pragma unroll
            for (int k = 0; k < NCG; k++)
                acc2[k] = fma2(e2[k], inv2, acc2[k]);

            // e[target]: group 0 handles pixel 0, group 1 handles pixel 1.
            // Reload is an L1 hit (line fetched by a same-warp thread).
            if (g == 0 && m0) {
                const float et = exp_scalar(pred[(size_t)b * C * HW + (size_t)t2.x * HW + base]);
                atomicAdd(&sh_inter[warp][t2.x], et * inv0);
                atomicAdd(&sh_cnt  [warp][t2.x], 1.0f);
            }
            if (g == 1 && m1) {
                const float et = exp_scalar(pred[(size_t)b * C * HW + (size_t)t2.y * HW + base + 1]);
                atomicAdd(&sh_inter[warp][t2.y], et * inv1);
                atomicAdd(&sh_cnt  [warp][t2.y], 1.0f);
            }
        }
    }

    // Reduce across the 8 same-g lanes of the warp (xor 4/8/16 keeps lane&3),
    // then lanes 0..3 (lane == g) publish their class slots.
    #pragma unroll
    for (int k = 0; k < NCG; k++) {
        float lo, hi;
        upk2f(acc2[k], lo, hi);
        float v = lo + hi;
        v += __shfl_xor_sync(0xffffffffu, v, 4);
        v += __shfl_xor_sync(0xffffffffu, v, 8);
        v += __shfl_xor_sync(0xffffffffu, v, 16);
        if (lane < CG) {
            const int cls = lane * NCG + k;
            if (cls < C) sh_pm[warp][cls] = v;
        }
    }
    __syncthreads();

    // Fixed-order fold across the 8 warps -> per-block partials.
    if (tid < C) {
        float pm = 0.0f, it = 0.0f, ct = 0.0f;
        #pragma unroll
        for (int w = 0; w < 8; w++) {
            pm += sh_pm[w][tid];
            it += sh_inter[w][tid];
            ct += sh_cnt[w][tid];
        }
        g_pm   [blk * C + tid] = pm;
        g_inter[blk * C + tid] = it;
        g_cnt  [blk * C + tid] = ct;
        __threadfence();                       // publish before counting
    }
    __syncthreads();

    if (tid == 0) {
        const int old = atomicAdd(&g_done, 1);
        sh_last = (old == NBLK - 1);
    }
    __syncthreads();
    if (!sh_last) return;

    // ---- last-block finalize (partials are L2-hot) ----
    __threadfence();                           // acquire partials
    __shared__ float sh_red[BLOCK];
    float v = 0.0f;
    if (tid < B * C) {
        const int bb = tid / C;
        const int cls = tid % C;
        float pm = 0.0f, it = 0.0f, ct = 0.0f;
        const int base = bb * GRPS_PER_BATCH;
        #pragma unroll 8
        for (int k = 0; k < GRPS_PER_BATCH; k++) {
            const int idx = (base + k) * C + cls;
            pm += g_pm[idx];
            it += g_inter[idx];
            ct += g_cnt[idx];
        }
        const float uni = pm + ct;
        const float dc  = (2.0f * it + SMOOTH) / (uni + SMOOTH);
        v = 1.0f - dc;
    }
    sh_red[tid] = v;
    __syncthreads();
    #pragma unroll
    for (int s = 128; s > 0; s >>= 1) {
        if (tid < s) sh_red[tid] += sh_red[tid + s];
        __syncthreads();
    }
    if (tid == 0) {
        out[0] = sh_red[0] * (1.0f / (float)(B * C));
        g_done = 0;                            // reset for next (graph) launch
    }
}

extern "C" void kernel_launch(void* const* d_in, const int* in_sizes, int n_in,
                              void* d_out, int out_size) {
    const float* pred   = (const float*)d_in[0];
    const int*   target = (const int*)d_in[1];
    float*       out    = (float*)d_out;
    (void)in_sizes; (void)n_in; (void)out_size;

    dice_main_kernel<<<NBLK, BLOCK>>>(pred, target, out);
}

// round 16
// speedup vs baseline: 1.4144x; 1.0122x over previous
#include <cuda_runtime.h>
#include <cuda_bf16.h>
#include <cstdint>

// DiceLoss: pred (8,19,512,512) fp32 logits, target (8,512,512) int32 -> scalar fp32.
//
// Single fused kernel:
//  * 19 classes split across 4 threads (g = tid&3 owns 5 slots, last padded)
//    -> ~20 regs packed state, 4 blocks/SM. Softmax sum via 2 packed butterflies.
//  * e[target] is SELECTED FROM REGISTERS (5-way predicated select + the same
//    butterfly) instead of a gather reload -- the gather was ~44% of all L1
//    wavefronts and a fully dependent load chain.
//  * 512 blocks x 2 chunks -> single resident wave at 4 blocks/SM.
//  * Packed f32x2 deg-3 polynomial exp on the FMA pipe (no MUFU).
//  * Per-warp shared atomics for intersection/count.
//  * Last-block-done finalize; counter self-resets (graph-replay safe).

static constexpr int B   = 8;
static constexpr int C   = 19;
static constexpr int CG  = 4;                   // class groups (threads per pixel-pair)
static constexpr int NCG = 5;                   // class slots per group (last padded)
static constexpr int HW  = 512 * 512;           // 262144
static constexpr int BLOCK = 256;
static constexpr int PAIRS_PER_ITER = BLOCK / CG;              // 64 pixel-pairs
static constexpr int ITERS = 16;                               // per chunk
static constexpr int PIX_PER_CHUNK = PAIRS_PER_ITER * 2 * ITERS;   // 2048
static constexpr int CHUNKS_PER_BATCH = HW / PIX_PER_CHUNK;    // 128
static constexpr int CHUNKS_PER_BLK = 2;
static constexpr int GRPS_PER_BATCH = CHUNKS_PER_BATCH / CHUNKS_PER_BLK;  // 64
static constexpr int NBLK = B * GRPS_PER_BATCH;                // 512 (single wave)
static constexpr float SMOOTH = 1e-5f;
static constexpr int IGNORE_INDEX = 255;

// Scratch partials (fully overwritten every launch -> no init needed).
__device__ float g_pm   [NBLK * C];
__device__ float g_inter[NBLK * C];
__device__ float g_cnt  [NBLK * C];
__device__ int   g_done;                        // zero-init; reset by final block

// ---------- packed f32x2 helpers (Blackwell sm_103a) ----------
__device__ __forceinline__ unsigned long long pk2(float a, float b) {
    unsigned long long r;
    asm("mov.b64 %0, {%1, %2};" : "=l"(r) : "f"(a), "f"(b));
    return r;
}
__device__ __forceinline__ unsigned long long add2(unsigned long long a, unsigned long long b) {
    unsigned long long r;
    asm("add.rn.f32x2 %0, %1, %2;" : "=l"(r) : "l"(a), "l"(b));
    return r;
}
__device__ __forceinline__ unsigned long long fma2(unsigned long long a, unsigned long long b,
                                                   unsigned long long c) {
    unsigned long long r;
    asm("fma.rn.f32x2 %0, %1, %2, %3;" : "=l"(r) : "l"(a), "l"(b), "l"(c));
    return r;
}
__device__ __forceinline__ void upk2f(unsigned long long v, float& a, float& b) {
    asm("mov.b64 {%0, %1}, %2;" : "=f"(a), "=f"(b) : "l"(v));
}
__device__ __forceinline__ void upk2u(unsigned long long v, unsigned& a, unsigned& b) {
    asm("mov.b64 {%0, %1}, %2;" : "=r"(a), "=r"(b) : "l"(v));
}
__device__ __forceinline__ unsigned long long pk2u(unsigned a, unsigned b) {
    unsigned long long r;
    asm("mov.b64 %0, {%1, %2};" : "=l"(r) : "r"(a), "r"(b));
    return r;
}
__device__ __forceinline__ unsigned long long shfl2_xor(unsigned long long v, int m) {
    unsigned lo, hi;
    upk2u(v, lo, hi);
    lo = __shfl_xor_sync(0xffffffffu, lo, m);
    hi = __shfl_xor_sync(0xffffffffu, hi, m);
    return pk2u(lo, hi);
}

// exp: deg-3 poly for 2^f on f in [-0.5,0.5], Chebyshev-corrected (rel err
// ~1e-4; cancels to ~1e-5 in the final dice ratio). Evaluated in
// G = round(t) - t = -f, so odd coefficients carry flipped sign.
#define EXP_L2E   1.4426950408889634f
#define EXP_NL2E  (-1.4426950408889634f)
#define EXP_MAGIC 12582912.0f                   // 1.5 * 2^23
#define EXP_PC0   0.99992486f
#define EXP_NC1   (-0.69312114f)
#define EXP_PC2   0.24263101f
#define EXP_NC3   (-0.05592081f)

// e^x for two floats at once. Z = fma(x, log2e, MAGIC): mantissa low bits hold
// round(t); (bits(Z) << 23) == round(t) << 23 (mod 2^32) -> exponent splice is
// one shift+add per half on the alu pipe. 6 fma-pipe ops total.
__device__ __forceinline__ unsigned long long exp_pair(float x0, float x1) {
    const unsigned long long L2E2  = pk2(EXP_L2E, EXP_L2E);
    const unsigned long long NL2E2 = pk2(EXP_NL2E, EXP_NL2E);
    const unsigned long long MG2   = pk2(EXP_MAGIC, EXP_MAGIC);
    const unsigned long long NMG2  = pk2(-EXP_MAGIC, -EXP_MAGIC);
    const unsigned long long K3    = pk2(EXP_NC3, EXP_NC3);
    const unsigned long long K2    = pk2(EXP_PC2, EXP_PC2);
    const unsigned long long K1    = pk2(EXP_NC1, EXP_NC1);
    const unsigned long long K0    = pk2(EXP_PC0, EXP_PC0);

    unsigned long long X = pk2(x0, x1);
    unsigned long long Z = fma2(X, L2E2, MG2);   // bits: base + round(t)
    unsigned long long R = add2(Z, NMG2);        // round(t) as float
    unsigned long long G = fma2(X, NL2E2, R);    // -f, in [-0.5, 0.5]
    unsigned long long P = fma2(K3, G, K2);
    P = fma2(P, G, K1);
    P = fma2(P, G, K0);
    unsigned z0, z1, p0, p1;
    upk2u(Z, z0, z1);
    upk2u(P, p0, p1);
    return pk2u(p0 + (z0 << 23), p1 + (z1 << 23));
}

__global__ __launch_bounds__(BLOCK, 4)
void dice_main_kernel(const float* __restrict__ pred,
                      const int*   __restrict__ target,
                      float*       __restrict__ out) {
    const int blk   = blockIdx.x;
    const int b     = blk / GRPS_PER_BATCH;
    const int grp   = blk % GRPS_PER_BATCH;      // chunk group within batch
    const int tid   = threadIdx.x;
    const int warp  = tid >> 5;
    const int lane  = tid & 31;
    const int g     = tid & (CG - 1);            // class group 0..3
    const int pix   = tid >> 2;                  // pixel-pair slot 0..63
    const int cbase = g * NCG;                   // first class of this group

    __shared__ float sh_inter[8][C];   // per-warp privatized
    __shared__ float sh_cnt  [8][C];
    __shared__ float sh_pm   [8][C];
    __shared__ int   sh_last;

    for (int i = tid; i < 8 * C; i += BLOCK) {
        (&sh_inter[0][0])[i] = 0.0f;
        (&sh_cnt  [0][0])[i] = 0.0f;
    }
    __syncthreads();

    const float* __restrict__ pbg = pred + (size_t)b * C * HW + (size_t)cbase * HW;
    const int*   __restrict__ tb  = target + (size_t)b * HW;
    const bool has_pad = (g == CG - 1);          // group 3: slot 4 is padding

    // Packed per-class-slot accumulators; halves = the two pixels of a pair.
    unsigned long long acc2[NCG];
    #pragma unroll
    for (int k = 0; k < NCG; k++) acc2[k] = pk2(0.0f, 0.0f);

    for (int cc = 0; cc < CHUNKS_PER_BLK; cc++) {
        const int chunk = grp + cc * GRPS_PER_BATCH;   // grp and grp+64
        const int hw0 = chunk * PIX_PER_CHUNK;

        #pragma unroll 4
        for (int j = 0; j < ITERS; j++) {
            const int base = hw0 + j * (PAIRS_PER_ITER * 2) + pix * 2;
            const int2 t2 = *(const int2*)(tb + base);

            unsigned long long e2[NCG];
            #pragma unroll
            for (int k = 0; k < NCG; k++) {
                float2 x;
                if (k == NCG - 1 && has_pad) {
                    x.x = -88.0f; x.y = -88.0f;  // pad slot -> exp ~ 0
                } else {
                    x = *(const float2*)(pbg + (size_t)k * HW + base);
                }
                e2[k] = exp_pair(x.x, x.y);
            }
            // Tree-sum this thread's 5 slots (depth 3), then butterfly across
            // the 4 class groups (lanes g0..g3 of the same pixel pair).
            unsigned long long S2 = add2(add2(e2[0], e2[1]), add2(e2[2], e2[3]));
            S2 = add2(S2, e2[4]);
            S2 = add2(S2, shfl2_xor(S2, 1));
            S2 = add2(S2, shfl2_xor(S2, 2));

            // e[target] for both pixels: select from registers (the owning
            // group contributes its slot; others contribute 0), then the same
            // butterfly-add broadcasts it to all 4 groups. No memory gather.
            unsigned et0 = 0u, et1 = 0u;
            #pragma unroll
            for (int k = 0; k < NCG; k++) {
                unsigned lo, hi;
                upk2u(e2[k], lo, hi);
                if (cbase + k == t2.x) et0 = lo;   // pixel 0 value is lo half
                if (cbase + k == t2.y) et1 = hi;   // pixel 1 value is hi half
            }
            unsigned long long ET2 = pk2u(et0, et1);
            ET2 = add2(ET2, shfl2_xor(ET2, 1));
            ET2 = add2(ET2, shfl2_xor(ET2, 2));

            float s0, s1;
            upk2f(S2, s0, s1);
            const bool m0 = (t2.x != IGNORE_INDEX);
            const bool m1 = (t2.y != IGNORE_INDEX);
            const float inv0 = m0 ? __fdividef(1.0f, s0) : 0.0f;  // MUFU.RCP
            const float inv1 = m1 ? __fdividef(1.0f, s1) : 0.0f;
            const unsigned long long inv2 = pk2(inv0, inv1);

            #pragma unroll
            for (int k = 0; k < NCG; k++)
                acc2[k] = fma2(e2[k], inv2, acc2[k]);

            float et0f, et1f;
            upk2f(ET2, et0f, et1f);
            if (g == 0 && m0) {
                atomicAdd(&sh_inter[warp][t2.x], et0f * inv0);
                atomicAdd(&sh_cnt  [warp][t2.x], 1.0f);
            }
            if (g == 1 && m1) {
                atomicAdd(&sh_inter[warp][t2.y], et1f * inv1);
                atomicAdd(&sh_cnt  [warp][t2.y], 1.0f);
            }
        }
    }

    // Reduce across the 8 same-g lanes of the warp (xor 4/8/16 keeps lane&3),
    // then lanes 0..3 (lane == g) publish their class slots.
    #pragma unroll
    for (int k = 0; k < NCG; k++) {
        float lo, hi;
        upk2f(acc2[k], lo, hi);
        float v = lo + hi;
        v += __shfl_xor_sync(0xffffffffu, v, 4);
        v += __shfl_xor_sync(0xffffffffu, v, 8);
        v += __shfl_xor_sync(0xffffffffu, v, 16);
        if (lane < CG) {
            const int cls = lane * NCG + k;
            if (cls < C) sh_pm[warp][cls] = v;
        }
    }
    __syncthreads();

    // Fixed-order fold across the 8 warps -> per-block partials.
    if (tid < C) {
        float pm = 0.0f, it = 0.0f, ct = 0.0f;
        #pragma unroll
        for (int w = 0; w < 8; w++) {
            pm += sh_pm[w][tid];
            it += sh_inter[w][tid];
            ct += sh_cnt[w][tid];
        }
        g_pm   [blk * C + tid] = pm;
        g_inter[blk * C + tid] = it;
        g_cnt  [blk * C + tid] = ct;
        __threadfence();                       // publish before counting
    }
    __syncthreads();

    if (tid == 0) {
        const int old = atomicAdd(&g_done, 1);
        sh_last = (old == NBLK - 1);
    }
    __syncthreads();
    if (!sh_last) return;

    // ---- last-block finalize (partials are L2-hot) ----
    __threadfence();                           // acquire partials
    __shared__ float sh_red[BLOCK];
    float v = 0.0f;
    if (tid < B * C) {
        const int bb = tid / C;
        const int cls = tid % C;
        float pm = 0.0f, it = 0.0f, ct = 0.0f;
        const int base = bb * GRPS_PER_BATCH;
        #pragma unroll 8
        for (int k = 0; k < GRPS_PER_BATCH; k++) {
            const int idx = (base + k) * C + cls;
            pm += g_pm[idx];
            it += g_inter[idx];
            ct += g_cnt[idx];
        }
        const float uni = pm + ct;
        const float dc  = (2.0f * it + SMOOTH) / (uni + SMOOTH);
        v = 1.0f - dc;
    }
    sh_red[tid] = v;
    __syncthreads();
    #pragma unroll
    for (int s = 128; s > 0; s >>= 1) {
        if (tid < s) sh_red[tid] += sh_red[tid + s];
        __syncthreads();
    }
    if (tid == 0) {
        out[0] = sh_red[0] * (1.0f / (float)(B * C));
        g_done = 0;                            // reset for next (graph) launch
    }
}

extern "C" void kernel_launch(void* const* d_in, const int* in_sizes, int n_in,
                              void* d_out, int out_size) {
    const float* pred   = (const float*)d_in[0];
    const int*   target = (const int*)d_in[1];
    float*       out    = (float*)d_out;
    (void)in_sizes; (void)n_in; (void)out_size;

    dice_main_kernel<<<NBLK, BLOCK>>>(pred, target, out);
}